// round 6
// baseline (speedup 1.0000x reference)
#include <cuda_runtime.h>
#include <cuda_fp16.h>
#include <cstdint>

// ============================================================================
// LocationAwareAttention  B=32, S=2048, D=512   (family-common PTX only:
// mma.sync.m16n8k16.f16 + ldmatrix + cp.async — NO tcgen05, target is sm_103)
//
// R6: convoy-breaking. R4/R5 showed dur invariant to warps-per-CTA with no
// pipe saturated -> single-CTA barrier phases convoy all warps. Split into
// block tile M=64 x N=256 (87KB smem) so 2 independent CTAs share each SM;
// one CTA's mma burst overlaps the other's load/sync phase.
// Scores d-reduction now spans 2 blocks -> atomicAdd into zeroed g_scores
// (score_b dropped: softmax is shift-invariant).
// 3 launches: prep_all, scores, softmax+context fused.
// Output: d_out = [ctx (B*D) | align (B*S)] fp32
// ============================================================================

#define BB 32
#define SS 2048
#define DD 512

__device__ __half g_wvt[DD * DD];     // w_v^T [n][k] fp16
__device__ float  g_qw[BB * DD];      // q@w_q + bias + conv_b
__device__ float  g_scores[BB * SS];

// ---------------- SMEM layout (bytes), per CTA total 88832 ----------------
#define SM_B0   0                      // B: 2 stages x (256n x 64k fp16 = 32KB)
#define SM_BSZ  32768
#define SM_A0   65536                  // A: 2 stages x (64 x 64 fp16 = 8KB)
#define SM_A1   73728
#define SM_QWB  81920                  // 256 f32 (this block's d-half)
#define SM_CW0  (SM_QWB + 1024)
#define SM_CW1  (SM_CW0 + 1024)
#define SM_CW2  (SM_CW1 + 1024)
#define SM_SW   (SM_CW2 + 1024)
#define SM_E0   (SM_SW + 1024)         // 64 f32
#define SM_E1   (SM_E0 + 256)
#define SM_E2   (SM_E1 + 256)
#define SM_RED  (SM_E2 + 256)          // 64 rows x 4 ngroups f32
#define SM_TOT  (SM_RED + 1024)        // 88832 B  (x2 CTAs = 177664 < 227KB)

// ---------------- PTX helpers ----------------
__device__ __forceinline__ uint32_t s2u(const void* p) {
    uint32_t a;
    asm("{ .reg .u64 t; cvta.to.shared.u64 t, %1; cvt.u32.u64 %0, t; }"
        : "=r"(a) : "l"(p));
    return a;
}
__device__ __forceinline__ void cp16(uint32_t dst, const void* src) {
    asm volatile("cp.async.ca.shared.global [%0], [%1], 16;"
                 :: "r"(dst), "l"(src) : "memory");
}
__device__ __forceinline__ void cp_commit() {
    asm volatile("cp.async.commit_group;" ::: "memory");
}
__device__ __forceinline__ void cp_wait0() {
    asm volatile("cp.async.wait_group 0;" ::: "memory");
}
__device__ __forceinline__ void ldsm4(uint32_t& r0, uint32_t& r1,
                                      uint32_t& r2, uint32_t& r3, uint32_t a) {
    asm volatile("ldmatrix.sync.aligned.m8n8.x4.shared.b16 {%0,%1,%2,%3}, [%4];"
                 : "=r"(r0), "=r"(r1), "=r"(r2), "=r"(r3) : "r"(a));
}
__device__ __forceinline__ void mma16816(float* d, const uint32_t* a,
                                         const uint32_t* b) {
    asm volatile(
        "mma.sync.aligned.m16n8k16.row.col.f32.f16.f16.f32 "
        "{%0,%1,%2,%3}, {%4,%5,%6,%7}, {%8,%9}, {%0,%1,%2,%3};"
        : "+f"(d[0]), "+f"(d[1]), "+f"(d[2]), "+f"(d[3])
        : "r"(a[0]), "r"(a[1]), "r"(a[2]), "r"(a[3]), "r"(b[0]), "r"(b[1]));
}
__device__ __forceinline__ uint32_t packh(__half a, __half b) {
    __half2 h2; h2.x = a; h2.y = b;
    return *(uint32_t*)&h2;
}
__device__ __forceinline__ uint32_t swz(uint32_t row, uint32_t colByte) {
    return row * 128u + (colByte ^ ((row & 7u) << 4));
}

// ============================================================================
// prep_all: one launch.
//   blocks [0,512):    g_wvt row n = blockIdx  (w_v^T -> fp16)
//   blocks [512,576):  g_qw for (b, dhalf)
//   blocks [576,608):  zero g_scores for batch b
// ============================================================================
__global__ void __launch_bounds__(256)
prep_all_kernel(const float* __restrict__ w_v,
                const float* __restrict__ query,
                const float* __restrict__ w_q,
                const float* __restrict__ bias,
                const float* __restrict__ conv_b) {
    int blk = blockIdx.x, tid = threadIdx.x;
    if (blk < 512) {
        int n = blk;
        for (int k = tid; k < DD; k += 256)
            g_wvt[n * DD + k] = __float2half_rn(w_v[k * DD + n]);
    } else if (blk < 576) {
        __shared__ float qs[DD];
        int b = (blk - 512) >> 1, dh = (blk - 512) & 1;
        int d = dh * 256 + tid;
        qs[tid]       = query[b * DD + tid];
        qs[tid + 256] = query[b * DD + tid + 256];
        __syncthreads();
        float a0 = 0.f, a1 = 0.f, a2 = 0.f, a3 = 0.f;
        float a4 = 0.f, a5 = 0.f, a6 = 0.f, a7 = 0.f;
#pragma unroll 8
        for (int k = 0; k < DD; k += 8) {
            a0 = fmaf(qs[k],     w_q[(k)     * DD + d], a0);
            a1 = fmaf(qs[k + 1], w_q[(k + 1) * DD + d], a1);
            a2 = fmaf(qs[k + 2], w_q[(k + 2) * DD + d], a2);
            a3 = fmaf(qs[k + 3], w_q[(k + 3) * DD + d], a3);
            a4 = fmaf(qs[k + 4], w_q[(k + 4) * DD + d], a4);
            a5 = fmaf(qs[k + 5], w_q[(k + 5) * DD + d], a5);
            a6 = fmaf(qs[k + 6], w_q[(k + 6) * DD + d], a6);
            a7 = fmaf(qs[k + 7], w_q[(k + 7) * DD + d], a7);
        }
        g_qw[b * DD + d] = bias[d] + conv_b[d]
                         + ((a0 + a1) + (a2 + a3)) + ((a4 + a5) + (a6 + a7));
    } else {
        int b = blk - 576;
        for (int j = tid; j < SS; j += 256)
            g_scores[b * SS + j] = 0.f;
    }
}

// ============================================================================
// scores: block tile M=64 x N=256 (half of D), K=512, fp16 mma, fp32 accum.
// Grid 2048 = (b, stile, nh); 256 threads / 8 warps, warp tile 32x64.
// 2 CTAs per SM (88KB smem each) -> phase overlap across CTAs.
// Partial score (over 256 d) -> atomicAdd into g_scores.
// ============================================================================
__global__ void __launch_bounds__(256, 2)
scores_kernel(const float* __restrict__ value,
              const float* __restrict__ energy,
              const float* __restrict__ conv_w,
              const float* __restrict__ score_w) {
    extern __shared__ char smem[];
    const uint32_t sb = s2u(smem);
    const int tid = threadIdx.x, wid = tid >> 5, lid = tid & 31;
    const int mg = wid >> 2;           // 0..1 : m rows [mg*32, +32)
    const int ngl = wid & 3;           // 0..3 : n cols [ngl*64, +64) in half
    const int b = blockIdx.x >> 6;
    const int stile = (blockIdx.x >> 1) & 31;
    const int nh = blockIdx.x & 1;     // which 256-wide d-half
    const int s0 = stile * 64;
    const int dbase = nh * 256;
    const size_t grow0 = (size_t)b * SS + s0;

    // ---- epilogue constants (this block's 256 d-cols) ----
    float* c_qwb = (float*)(smem + SM_QWB);
    float* c_cw0 = (float*)(smem + SM_CW0);
    float* c_cw1 = (float*)(smem + SM_CW1);
    float* c_cw2 = (float*)(smem + SM_CW2);
    float* c_sw  = (float*)(smem + SM_SW);
    {
        int gd = dbase + tid;
        c_qwb[tid] = g_qw[b * DD + gd];
        c_cw0[tid] = conv_w[gd * 3 + 0];
        c_cw1[tid] = conv_w[gd * 3 + 1];
        c_cw2[tid] = conv_w[gd * 3 + 2];
        c_sw[tid]  = score_w[gd];
    }
    if (tid < 64) {
        int s = s0 + tid, gs = b * SS + s;
        ((float*)(smem + SM_E1))[tid] = energy[gs];
        ((float*)(smem + SM_E0))[tid] = (s > 0)      ? energy[gs - 1] : 0.f;
        ((float*)(smem + SM_E2))[tid] = (s < SS - 1) ? energy[gs + 1] : 0.f;
    }

    float4 pre[4];  // prefetched A fp32 (2 tasks x 8 floats)

    // A gmem->regs: 64 rows x 8 chunks of 8 floats = 512 tasks
    auto ldA = [&](int ch) {
        int kb = ch * 64;
#pragma unroll
        for (int q = 0; q < 2; ++q) {
            int t = tid * 2 + q, r = t >> 3, c = t & 7;
            const float4* src =
                (const float4*)(value + (grow0 + r) * DD + kb + c * 8);
            pre[q * 2]     = src[0];
            pre[q * 2 + 1] = src[1];
        }
    };
    auto stsA = [&](int ch) {
        char* ah = smem + ((ch & 1) ? SM_A1 : SM_A0);
#pragma unroll
        for (int q = 0; q < 2; ++q) {
            int t = tid * 2 + q, r = t >> 3, c = t & 7;
            uint32_t off = swz((uint32_t)r, (uint32_t)c * 16);
            uint32_t hh[4];
#pragma unroll
            for (int j = 0; j < 2; ++j) {
                float4 v = pre[q * 2 + j];
                hh[j * 2]     = packh(__float2half_rn(v.x), __float2half_rn(v.y));
                hh[j * 2 + 1] = packh(__float2half_rn(v.z), __float2half_rn(v.w));
            }
            *(uint4*)(ah + off) = make_uint4(hh[0], hh[1], hh[2], hh[3]);
        }
    };
    // B tile: 256n x 64k fp16 = 2048 x 16B, 2-stage
    auto cpB = [&](int ch) {
        int kb = ch * 64;
        uint32_t bbuf = sb + SM_B0 + (uint32_t)(ch & 1) * SM_BSZ;
#pragma unroll
        for (int q = 0; q < 8; ++q) {
            int t = tid + q * 256, n = t >> 3, c = t & 7;
            cp16(bbuf + swz((uint32_t)n, (uint32_t)c * 16),
                 g_wvt + (size_t)(dbase + n) * DD + kb + c * 8);
        }
        cp_commit();
    };

    float acc[2][8][4];
#pragma unroll
    for (int i = 0; i < 2; ++i)
#pragma unroll
        for (int j = 0; j < 8; ++j)
#pragma unroll
            for (int c = 0; c < 4; ++c) acc[i][j][c] = 0.f;

    const int nwb = ngl * 64;
    const int mwb = mg * 32;

    auto compute = [&](int ch) {
        uint32_t abh = sb + ((ch & 1) ? SM_A1 : SM_A0);
        uint32_t bb  = sb + SM_B0 + (uint32_t)(ch & 1) * SM_BSZ;
#pragma unroll
        for (int s = 0; s < 4; ++s) {
            uint32_t bfr[8][2];
#pragma unroll
            for (int np = 0; np < 4; ++np) {
                uint32_t row = nwb + np * 16 + ((lid & 16) >> 1) + (lid & 7);
                uint32_t col = s * 32 + ((lid & 8) << 1);
                ldsm4(bfr[np * 2][0], bfr[np * 2][1],
                      bfr[np * 2 + 1][0], bfr[np * 2 + 1][1],
                      bb + swz(row, col));
            }
#pragma unroll
            for (int mi = 0; mi < 2; ++mi) {
                uint32_t row = mwb + mi * 16 + (lid & 15);
                uint32_t col = s * 32 + (lid & 16);
                uint32_t ah[4];
                ldsm4(ah[0], ah[1], ah[2], ah[3], abh + swz(row, col));
#pragma unroll
                for (int ni = 0; ni < 8; ++ni)
                    mma16816(acc[mi][ni], ah, bfr[ni]);
            }
        }
    };

    // ---- pipelined K loop (8 chunks of 64, B 1 chunk ahead; 2 CTAs/SM
    //      provide the cross-phase overlap) ----
    ldA(0);
    cpB(0);
    stsA(0);
    ldA(1);
    for (int ch = 0; ch < 8; ++ch) {
        cp_wait0();               // B(ch) arrived
        __syncthreads();          // A(ch) visible; compute(ch-1) done
        if (ch < 7) cpB(ch + 1);
        if (ch < 7) stsA(ch + 1);
        if (ch < 6) ldA(ch + 2);
        compute(ch);
    }

    // ---- epilogue: x = acc + qw + conv(e); partial = sum tanh(x)*sw ----
    const float* E0 = (const float*)(smem + SM_E0);
    const float* E1 = (const float*)(smem + SM_E1);
    const float* E2 = (const float*)(smem + SM_E2);
    float e0r[4], e1r[4], e2r[4];
#pragma unroll
    for (int mi = 0; mi < 2; ++mi)
#pragma unroll
        for (int h = 0; h < 2; ++h) {
            int r = mwb + mi * 16 + h * 8 + (lid >> 2);
            e0r[mi * 2 + h] = E0[r];
            e1r[mi * 2 + h] = E1[r];
            e2r[mi * 2 + h] = E2[r];
        }
    float part[4];
#pragma unroll
    for (int i = 0; i < 4; ++i) part[i] = 0.f;

#pragma unroll
    for (int ni = 0; ni < 8; ++ni) {
        int d0 = nwb + ni * 8 + 2 * (lid & 3);   // local 0..255
        float qb0 = c_qwb[d0], qb1 = c_qwb[d0 + 1];
        float w00 = c_cw0[d0], w01 = c_cw0[d0 + 1];
        float w10 = c_cw1[d0], w11 = c_cw1[d0 + 1];
        float w20 = c_cw2[d0], w21 = c_cw2[d0 + 1];
        float sw0 = c_sw[d0],  sw1 = c_sw[d0 + 1];
#pragma unroll
        for (int mi = 0; mi < 2; ++mi)
#pragma unroll
            for (int h = 0; h < 2; ++h) {
                int pi = mi * 2 + h;
                float x0 = acc[mi][ni][h * 2] + qb0
                         + e0r[pi] * w00 + e1r[pi] * w10 + e2r[pi] * w20;
                float x1 = acc[mi][ni][h * 2 + 1] + qb1
                         + e0r[pi] * w01 + e1r[pi] * w11 + e2r[pi] * w21;
                float t0 = 1.f - __fdividef(2.f, __expf(2.f * x0) + 1.f);
                float t1 = 1.f - __fdividef(2.f, __expf(2.f * x1) + 1.f);
                part[pi] = fmaf(t0, sw0, fmaf(t1, sw1, part[pi]));
            }
    }
#pragma unroll
    for (int pi = 0; pi < 4; ++pi) {
        part[pi] += __shfl_xor_sync(0xffffffffu, part[pi], 1);
        part[pi] += __shfl_xor_sync(0xffffffffu, part[pi], 2);
    }
    float* red = (float*)(smem + SM_RED);
    if ((lid & 3) == 0) {
#pragma unroll
        for (int mi = 0; mi < 2; ++mi)
#pragma unroll
            for (int h = 0; h < 2; ++h) {
                int r = mwb + mi * 16 + h * 8 + (lid >> 2);
                red[r * 4 + ngl] = part[mi * 2 + h];
            }
    }
    __syncthreads();
    if (tid < 64) {
        float sum = red[tid * 4] + red[tid * 4 + 1]
                  + red[tid * 4 + 2] + red[tid * 4 + 3];
        atomicAdd(&g_scores[b * SS + s0 + tid], sum);
    }
}

// ============================================================================
// softmax + context fused. Grid (32, 4): b, dch (128 d-cols each).
// Each block: softmax of row b from g_scores in smem (dch==0 writes align),
// then ctx[b, dch*128 + c] = sum_s align[s] * value[b,s,c]  (no atomics).
// Note: score_b omitted everywhere — softmax is shift-invariant.
// ============================================================================
__global__ void __launch_bounds__(256)
softmax_context_kernel(const float* __restrict__ value,
                       float* __restrict__ align_out,
                       float* __restrict__ ctx_out) {
    __shared__ float sc[SS];
    __shared__ float wred[8];
    __shared__ float pc[256];
    const int b = blockIdx.x, dch = blockIdx.y;
    const int t = threadIdx.x, w = t >> 5, l = t & 31;

    float v[8];
#pragma unroll
    for (int j = 0; j < 8; ++j) v[j] = g_scores[b * SS + t + j * 256];
    float m = v[0];
#pragma unroll
    for (int j = 1; j < 8; ++j) m = fmaxf(m, v[j]);
#pragma unroll
    for (int o = 16; o > 0; o >>= 1)
        m = fmaxf(m, __shfl_xor_sync(0xffffffffu, m, o));
    if (l == 0) wred[w] = m;
    __syncthreads();
    m = wred[0];
#pragma unroll
    for (int i = 1; i < 8; ++i) m = fmaxf(m, wred[i]);
    __syncthreads();

    float e[8], sum = 0.f;
#pragma unroll
    for (int j = 0; j < 8; ++j) { e[j] = __expf(v[j] - m); sum += e[j]; }
#pragma unroll
    for (int o = 16; o > 0; o >>= 1)
        sum += __shfl_xor_sync(0xffffffffu, sum, o);
    if (l == 0) wred[w] = sum;
    __syncthreads();
    sum = wred[0];
#pragma unroll
    for (int i = 1; i < 8; ++i) sum += wred[i];
    float inv = 1.f / sum;
#pragma unroll
    for (int j = 0; j < 8; ++j) {
        float a = e[j] * inv;
        sc[t + j * 256] = a;
        if (dch == 0) align_out[b * SS + t + j * 256] = a;
    }
    __syncthreads();

    // context: thread t -> col (t&127), s-half (t>>7)
    const int col = dch * 128 + (t & 127);
    const int sh = t >> 7;
    const float* vb = value + ((size_t)b * SS + sh * 1024) * DD + col;
    const float* ab = sc + sh * 1024;
    float a0 = 0.f, a1 = 0.f;
#pragma unroll 4
    for (int s = 0; s < 1024; s += 2) {
        a0 = fmaf(ab[s],     vb[(size_t)s * DD],       a0);
        a1 = fmaf(ab[s + 1], vb[(size_t)(s + 1) * DD], a1);
    }
    pc[t] = a0 + a1;
    __syncthreads();
    if (t < 128) ctx_out[b * DD + dch * 128 + t] = pc[t] + pc[t + 128];
}

// ============================================================================
// launch
// ============================================================================
extern "C" void kernel_launch(void* const* d_in, const int* in_sizes, int n_in,
                              void* d_out, int out_size) {
    const float* query   = (const float*)d_in[0];
    const float* value   = (const float*)d_in[1];
    const float* energy  = (const float*)d_in[2];
    const float* conv_w  = (const float*)d_in[3];
    const float* conv_b  = (const float*)d_in[4];
    const float* w_q     = (const float*)d_in[5];
    const float* w_v     = (const float*)d_in[6];
    const float* bias    = (const float*)d_in[7];
    const float* score_w = (const float*)d_in[8];
    float* out_ctx   = (float*)d_out;            // [B*D]
    float* out_align = (float*)d_out + BB * DD;  // [B*S]

    cudaFuncSetAttribute(scores_kernel,
                         cudaFuncAttributeMaxDynamicSharedMemorySize, SM_TOT);

    prep_all_kernel<<<608, 256>>>(w_v, query, w_q, bias, conv_b);
    scores_kernel<<<BB * 32 * 2, 256, SM_TOT>>>(value, energy, conv_w, score_w);
    softmax_context_kernel<<<dim3(BB, 4), 256>>>(value, out_align, out_ctx);
}